// round 5
// baseline (speedup 1.0000x reference)
#include <cuda_runtime.h>

// softmax(f[n]+g[m]) over m cancels f[n] -> all output rows identical.
// K1: 32 CTAs reduce x with exp(g) weights -> partials transposed [17][32]
// K2: 128 CTAs: warp-per-column reduce partials, compute 128-float row, broadcast.
// Graph edge between K1/K2 provides the global sync (measured ~free).

#define D_IN 16
#define DH   18
#define K1_BLOCKS 32
#define K1_THREADS 256            // 32*256 = 8192 rows, 1 row/thread
#define K2_BLOCKS 128
#define K2_THREADS 544            // 17 warps
#define ROWS_PER_B2 (8192 / K2_BLOCKS)   // 64

__device__ float g_part[17 * K1_BLOCKS];   // [col][block]

__global__ void __launch_bounds__(K1_THREADS, 1) k1_reduce(
    const float* __restrict__ x,
    const float* __restrict__ W,
    const float* __restrict__ a)
{
    __shared__ float wa2[16];
    __shared__ float wsum[8][18];   // 8 warps x 17 (+pad)
    int tid  = threadIdx.x;
    int warp = tid >> 5, lane = tid & 31;

    // issue x loads FIRST (independent of wa2) so they fly during the sync
    int m = blockIdx.x * K1_THREADS + tid;
    const float4* xr = reinterpret_cast<const float4*>(x + (size_t)m * D_IN);
    float4 x0 = xr[0], x1 = xr[1], x2 = xr[2], x3 = xr[3];

    if (tid < 16) {
        float s = 0.f;
        #pragma unroll
        for (int j = 0; j < DH; ++j) s += W[tid * DH + j] * a[DH + j];
        wa2[tid] = s;
    }
    __syncthreads();

    float xv[16] = { x0.x, x0.y, x0.z, x0.w,  x1.x, x1.y, x1.z, x1.w,
                     x2.x, x2.y, x2.z, x2.w,  x3.x, x3.y, x3.z, x3.w };
    float g = 0.f;
    #pragma unroll
    for (int k = 0; k < 16; ++k) g += xv[k] * wa2[k];
    float e = expf(g);              // g is small (|g|<~3): no max-shift needed

    float p[17];
    #pragma unroll
    for (int k = 0; k < 16; ++k) p[k] = e * xv[k];
    p[16] = e;

    #pragma unroll
    for (int off = 16; off > 0; off >>= 1) {
        #pragma unroll
        for (int i = 0; i < 17; ++i)
            p[i] += __shfl_down_sync(0xffffffffu, p[i], off);
    }
    if (lane == 0) {
        #pragma unroll
        for (int i = 0; i < 17; ++i) wsum[warp][i] = p[i];
    }
    __syncthreads();

    if (tid < 17) {
        float s = 0.f;
        #pragma unroll
        for (int w = 0; w < 8; ++w) s += wsum[w][tid];
        g_part[tid * K1_BLOCKS + blockIdx.x] = s;   // transposed for K2
    }
}

__global__ void __launch_bounds__(K2_THREADS, 1) k2_finish(
    const float* __restrict__ Wk,
    float* __restrict__ out)
{
    __shared__ float red[17];
    __shared__ float orow[128];
    int tid  = threadIdx.x;
    int warp = tid >> 5, lane = tid & 31;

    // warp w reduces column w: 32 contiguous floats, one coalesced load
    if (warp < 17) {
        float v = g_part[warp * K1_BLOCKS + lane];
        #pragma unroll
        for (int off = 16; off > 0; off >>= 1)
            v += __shfl_down_sync(0xffffffffu, v, off);
        if (lane == 0) red[warp] = v;
    }
    __syncthreads();

    if (tid < 128) {
        float invZ = 1.0f / red[16];
        int h = tid >> 4, d = tid & 15;
        const float* Wh = Wk + h * (D_IN * D_IN);
        float s = 0.f;
        #pragma unroll
        for (int k = 0; k < 16; ++k) s += red[k] * Wh[k * 16 + d];
        orow[tid] = s * invZ;
    }
    __syncthreads();

    // broadcast: 64 rows/CTA = 2048 float4, 512 threads x 4 stores
    if (tid < 512) {
        int c4 = tid & 31;          // float4 column
        int r0 = tid >> 5;          // 0..15
        float4 val = make_float4(orow[c4 * 4 + 0], orow[c4 * 4 + 1],
                                 orow[c4 * 4 + 2], orow[c4 * 4 + 3]);
        float4* o4 = reinterpret_cast<float4*>(out);
        int rowbase = blockIdx.x * ROWS_PER_B2;
        #pragma unroll
        for (int i = 0; i < 4; ++i) {
            int r = rowbase + r0 + i * 16;
            o4[(size_t)r * 32 + c4] = val;
        }
    }
}

extern "C" void kernel_launch(void* const* d_in, const int* in_sizes, int n_in,
                              void* d_out, int out_size) {
    const float* x  = (const float*)d_in[0];  // (8192,16)
    const float* W  = (const float*)d_in[1];  // (16,18)
    const float* a  = (const float*)d_in[2];  // (36,1)
    const float* Wk = (const float*)d_in[3];  // (8,16,16)
    float* out = (float*)d_out;               // (8192,128)

    k1_reduce<<<K1_BLOCKS, K1_THREADS>>>(x, W, a);
    k2_finish<<<K2_BLOCKS, K2_THREADS>>>(Wk, out);
}

// round 6
// speedup vs baseline: 1.0332x; 1.0332x over previous
#include <cuda_runtime.h>

// softmax(f[n]+g[m]) over m cancels f[n] -> all output rows identical.
// K1: 32 CTAs reduce x with exp(g) weights -> partials transposed [17][32]
// K2: 128 CTAs: warp-per-column reduce partials, compute 128-float row, broadcast.
// Graph edge between K1/K2 provides the global sync (measured ~free).

#define D_IN 16
#define DH   18
#define K1_BLOCKS 32
#define K1_THREADS 256            // 32*256 = 8192 rows, 1 row/thread
#define K2_BLOCKS 128
#define K2_THREADS 544            // 17 warps
#define ROWS_PER_B2 (8192 / K2_BLOCKS)   // 64

__device__ float g_part[17 * K1_BLOCKS];   // [col][block]

__global__ void __launch_bounds__(K1_THREADS, 1) k1_reduce(
    const float* __restrict__ x,
    const float* __restrict__ W,
    const float* __restrict__ a)
{
    __shared__ float wa2[16];
    __shared__ float wsum[8][18];   // 8 warps x 17 (+pad)
    int tid  = threadIdx.x;
    int warp = tid >> 5, lane = tid & 31;

    // issue x loads FIRST (independent of wa2) so they fly during the sync
    int m = blockIdx.x * K1_THREADS + tid;
    const float4* xr = reinterpret_cast<const float4*>(x + (size_t)m * D_IN);
    float4 x0 = xr[0], x1 = xr[1], x2 = xr[2], x3 = xr[3];

    if (tid < 16) {
        float s = 0.f;
        #pragma unroll
        for (int j = 0; j < DH; ++j) s += W[tid * DH + j] * a[DH + j];
        wa2[tid] = s;
    }
    __syncthreads();

    float xv[16] = { x0.x, x0.y, x0.z, x0.w,  x1.x, x1.y, x1.z, x1.w,
                     x2.x, x2.y, x2.z, x2.w,  x3.x, x3.y, x3.z, x3.w };
    float g = 0.f;
    #pragma unroll
    for (int k = 0; k < 16; ++k) g += xv[k] * wa2[k];
    float e = expf(g);              // g is small (|g|<~3): no max-shift needed

    float p[17];
    #pragma unroll
    for (int k = 0; k < 16; ++k) p[k] = e * xv[k];
    p[16] = e;

    #pragma unroll
    for (int off = 16; off > 0; off >>= 1) {
        #pragma unroll
        for (int i = 0; i < 17; ++i)
            p[i] += __shfl_down_sync(0xffffffffu, p[i], off);
    }
    if (lane == 0) {
        #pragma unroll
        for (int i = 0; i < 17; ++i) wsum[warp][i] = p[i];
    }
    __syncthreads();

    if (tid < 17) {
        float s = 0.f;
        #pragma unroll
        for (int w = 0; w < 8; ++w) s += wsum[w][tid];
        g_part[tid * K1_BLOCKS + blockIdx.x] = s;   // transposed for K2
    }
}

__global__ void __launch_bounds__(K2_THREADS, 1) k2_finish(
    const float* __restrict__ Wk,
    float* __restrict__ out)
{
    __shared__ float red[17];
    __shared__ float orow[128];
    int tid  = threadIdx.x;
    int warp = tid >> 5, lane = tid & 31;

    // warp w reduces column w: 32 contiguous floats, one coalesced load
    if (warp < 17) {
        float v = g_part[warp * K1_BLOCKS + lane];
        #pragma unroll
        for (int off = 16; off > 0; off >>= 1)
            v += __shfl_down_sync(0xffffffffu, v, off);
        if (lane == 0) red[warp] = v;
    }
    __syncthreads();

    if (tid < 128) {
        float invZ = 1.0f / red[16];
        int h = tid >> 4, d = tid & 15;
        const float* Wh = Wk + h * (D_IN * D_IN);
        float s = 0.f;
        #pragma unroll
        for (int k = 0; k < 16; ++k) s += red[k] * Wh[k * 16 + d];
        orow[tid] = s * invZ;
    }
    __syncthreads();

    // broadcast: 64 rows/CTA = 2048 float4, 512 threads x 4 stores
    if (tid < 512) {
        int c4 = tid & 31;          // float4 column
        int r0 = tid >> 5;          // 0..15
        float4 val = make_float4(orow[c4 * 4 + 0], orow[c4 * 4 + 1],
                                 orow[c4 * 4 + 2], orow[c4 * 4 + 3]);
        float4* o4 = reinterpret_cast<float4*>(out);
        int rowbase = blockIdx.x * ROWS_PER_B2;
        #pragma unroll
        for (int i = 0; i < 4; ++i) {
            int r = rowbase + r0 + i * 16;
            o4[(size_t)r * 32 + c4] = val;
        }
    }
}

extern "C" void kernel_launch(void* const* d_in, const int* in_sizes, int n_in,
                              void* d_out, int out_size) {
    const float* x  = (const float*)d_in[0];  // (8192,16)
    const float* W  = (const float*)d_in[1];  // (16,18)
    const float* a  = (const float*)d_in[2];  // (36,1)
    const float* Wk = (const float*)d_in[3];  // (8,16,16)
    float* out = (float*)d_out;               // (8192,128)

    k1_reduce<<<K1_BLOCKS, K1_THREADS>>>(x, W, a);
    k2_finish<<<K2_BLOCKS, K2_THREADS>>>(Wk, out);
}